// round 1
// baseline (speedup 1.0000x reference)
#include <cuda_runtime.h>

#define NMIX 160          // 5 * 32 mixing dims
#define MT1 32            // gemm1 token tile
#define KC 32             // gemm1 k chunk
#define MT2 16            // gemm2 token tile
#define DT2 128           // gemm2 d tile

// scratch for h = tanh(xk @ W1): M x 160 floats (M = 8192 for this problem)
__device__ float g_h[8192 * NMIX];

// ---------------------------------------------------------------------------
// Kernel 1: h[m, n] = tanh( sum_k xk[m,k] * W1[k,n] )
//   xk[m,k] = x[m,k] + sx[m,k]*tmx[k],  sx = prev - x
//   prev[m] = x[m-1] within a sequence, state[b, i1] at t==0
// grid.x = M/MT1, block = 160 threads (one per output column n)
// ---------------------------------------------------------------------------
__global__ void k_gemm1(const float* __restrict__ x,
                        const float* __restrict__ state,
                        const float* __restrict__ tmx,
                        const float* __restrict__ W1,
                        const int* __restrict__ i_ptr,
                        int S, int D, int rows)
{
    __shared__ float xk_s[MT1][KC + 1];
    const int m0 = blockIdx.x * MT1;
    const int n  = threadIdx.x;             // 0..159
    const int i1 = rows * i_ptr[0] + 1;

    float acc[MT1];
#pragma unroll
    for (int r = 0; r < MT1; r++) acc[r] = 0.f;

    for (int k0 = 0; k0 < D; k0 += KC) {
        // stage xk tile: MT1*KC elems cooperatively
        for (int idx = threadIdx.x; idx < MT1 * KC; idx += blockDim.x) {
            int r  = idx / KC;
            int kk = idx - r * KC;
            int m  = m0 + r;
            int t  = m % S;
            int g  = k0 + kk;
            float xv = x[(size_t)m * D + g];
            float prev;
            if (t == 0) {
                int b = m / S;
                prev = state[((size_t)b * rows + i1) * D + g];
            } else {
                prev = x[(size_t)(m - 1) * D + g];
            }
            xk_s[r][kk] = xv + (prev - xv) * __ldg(&tmx[g]);
        }
        __syncthreads();

#pragma unroll 4
        for (int kk = 0; kk < KC; kk++) {
            float w = W1[(size_t)(k0 + kk) * NMIX + n];   // coalesced over n
#pragma unroll
            for (int r = 0; r < MT1; r++)
                acc[r] += xk_s[r][kk] * w;                // broadcast LDS
        }
        __syncthreads();
    }

#pragma unroll
    for (int r = 0; r < MT1; r++)
        g_h[(size_t)(m0 + r) * NMIX + n] = tanhf(acc[r]);
}

// ---------------------------------------------------------------------------
// Kernel 2: fused mode-GEMM (K=32 per mode) + combine:
//   out[m, f, d] = x[m,d] + sx[m,d] * ( maa_f[d] + sum_k h[m, f*32+k] * W2[f,k,d] )
// grid: (M/MT2, D/DT2), block = DT2 threads (one per d column)
// ---------------------------------------------------------------------------
__global__ void k_gemm2(const float* __restrict__ x,
                        const float* __restrict__ state,
                        const float* __restrict__ W2,
                        const float* __restrict__ mk,
                        const float* __restrict__ mw,
                        const float* __restrict__ mv,
                        const float* __restrict__ mr,
                        const float* __restrict__ mg,
                        const int* __restrict__ i_ptr,
                        float* __restrict__ out,
                        int S, int D, int rows)
{
    __shared__ float h_s[MT2][NMIX];
    __shared__ float xv_s[MT2][DT2];
    __shared__ float sx_s[MT2][DT2];

    const int m0  = blockIdx.x * MT2;
    const int d0  = blockIdx.y * DT2;
    const int tid = threadIdx.x;
    const int i1  = rows * i_ptr[0] + 1;
    const int d   = d0 + tid;

    // stage h tile
    for (int idx = tid; idx < MT2 * NMIX; idx += DT2) {
        int r = idx / NMIX;
        int c = idx - r * NMIX;
        h_s[r][c] = g_h[(size_t)(m0 + r) * NMIX + c];
    }
    // stage x / sx columns
#pragma unroll
    for (int r = 0; r < MT2; r++) {
        int m = m0 + r;
        int t = m % S;
        float xv = x[(size_t)m * D + d];
        float prev;
        if (t == 0) {
            int b = m / S;
            prev = state[((size_t)b * rows + i1) * D + d];
        } else {
            prev = x[(size_t)(m - 1) * D + d];
        }
        xv_s[r][tid] = xv;
        sx_s[r][tid] = prev - xv;
    }
    __syncthreads();

    const float* maa[5] = { mk, mw, mv, mr, mg };

#pragma unroll
    for (int f = 0; f < 5; f++) {
        float w[32];
#pragma unroll
        for (int k = 0; k < 32; k++)
            w[k] = W2[((size_t)f * 32 + k) * D + d];      // coalesced over d
        float mf = __ldg(&maa[f][d]);

#pragma unroll 4
        for (int r = 0; r < MT2; r++) {
            float acc = 0.f;
#pragma unroll
            for (int k = 0; k < 32; k++)
                acc += h_s[r][f * 32 + k] * w[k];          // broadcast LDS
            int m = m0 + r;
            out[((size_t)m * 5 + f) * D + d] =
                xv_s[r][tid] + sx_s[r][tid] * (mf + acc);
        }
    }
}

// ---------------------------------------------------------------------------
// Kernel 3: new_state = state, with row i1 <- x[:, S-1, :]
// ---------------------------------------------------------------------------
__global__ void k_state(const float* __restrict__ x,
                        const float* __restrict__ state,
                        const int* __restrict__ i_ptr,
                        float* __restrict__ out_state,
                        int S, int D, int rows, int total)
{
    int idx = blockIdx.x * blockDim.x + threadIdx.x;
    if (idx >= total) return;
    int d = idx % D;
    int r = (idx / D) % rows;
    int b = idx / (D * rows);
    int i1 = rows * i_ptr[0] + 1;
    float v;
    if (r == i1)
        v = x[((size_t)b * S + (S - 1)) * D + d];
    else
        v = state[idx];
    out_state[idx] = v;
}

// ---------------------------------------------------------------------------
extern "C" void kernel_launch(void* const* d_in, const int* in_sizes, int n_in,
                              void* d_out, int out_size)
{
    const float* x     = (const float*)d_in[0];
    const float* state = (const float*)d_in[1];
    const float* tmx   = (const float*)d_in[2];
    const float* W1    = (const float*)d_in[3];
    const float* W2    = (const float*)d_in[4];
    const float* mk    = (const float*)d_in[5];
    const float* mw    = (const float*)d_in[6];
    const float* mv    = (const float*)d_in[7];
    const float* mr    = (const float*)d_in[8];
    const float* mg    = (const float*)d_in[9];
    const int*   ip    = (const int*)d_in[10];

    const int D    = in_sizes[2];            // 2048 (time_maa_x)
    const int M    = in_sizes[0] / D;        // B*S = 8192
    const int rows = 2 + D / 32;             // 2 + HEAD_SIZE = 66
    const int B    = in_sizes[1] / (rows * D);
    const int S    = M / B;

    float* out_x = (float*)d_out;
    const long long xsz = (long long)M * 5 * D;

    k_gemm1<<<M / MT1, NMIX>>>(x, state, tmx, W1, ip, S, D, rows);

    dim3 g2(M / MT2, D / DT2);
    k_gemm2<<<g2, DT2>>>(x, state, W2, mk, mw, mv, mr, mg, ip, out_x, S, D, rows);

    if ((long long)out_size > xsz) {
        float* out_state = out_x + xsz;
        int total = B * rows * D;
        k_state<<<(total + 255) / 256, 256>>>(x, state, ip, out_state, S, D, rows, total);
    }
}

// round 2
// speedup vs baseline: 1.2722x; 1.2722x over previous
#include <cuda_runtime.h>

#define NMIX 160
// gemm1 tiling
#define BM1 64
#define KC1 32
#define T1  320
// gemm2 tiling
#define MT2 32
#define C2  2
#define T2  128
#define DT2 (T2*C2)   // 256

typedef unsigned long long ull;

__device__ __forceinline__ ull pk2(float a, float b) {
    ull r; asm("mov.b64 %0,{%1,%2};" : "=l"(r) : "f"(a), "f"(b)); return r;
}
__device__ __forceinline__ void upk2(ull v, float& a, float& b) {
    asm("mov.b64 {%0,%1},%2;" : "=f"(a), "=f"(b) : "l"(v));
}
__device__ __forceinline__ ull f2fma(ull a, ull b, ull c) {
    ull d; asm("fma.rn.f32x2 %0,%1,%2,%3;" : "=l"(d) : "l"(a), "l"(b), "l"(c)); return d;
}

// scratch for h = tanh(xk @ W1): M x 160 floats (M = 8192 here)
__device__ float g_h[8192 * NMIX];

// ---------------------------------------------------------------------------
// GEMM1: h[m,n] = tanh( sum_k xk[m,k] * W1[k,n] ),  xk = x + (prev-x)*tmx
// block: 64 tokens x 160 n, 320 threads, thread tile 8m x 4n (packed n-pairs)
// ---------------------------------------------------------------------------
__global__ void __launch_bounds__(T1) k_gemm1(
    const float* __restrict__ x, const float* __restrict__ state,
    const float* __restrict__ tmx, const float* __restrict__ W1,
    const int* __restrict__ i_ptr, int S, int D, int rows)
{
    __shared__ float xk_s[KC1][BM1 + 4];   // transposed, row 68 floats (16B-aligned rows)
    __shared__ float w_s[KC1][NMIX];

    const int m0g = blockIdx.x * BM1;
    const int tid = threadIdx.x;
    // warp covers 16 consecutive n (cheap broadcast of w within warp)
    const int n0 = (tid & 3) * 4 + (tid >> 5) * 16;
    const int mt = ((tid >> 2) & 7) * 8;
    const int i1 = rows * i_ptr[0] + 1;

    ull acc[8][2];
#pragma unroll
    for (int r = 0; r < 8; r++) { acc[r][0] = 0ull; acc[r][1] = 0ull; }

    for (int kk = 0; kk < D; kk += KC1) {
        __syncthreads();
        // stage xk (transposed) : 64m x 32k
        for (int idx = tid; idx < BM1 * KC1 / 4; idx += T1) {
            int m  = idx >> 3;
            int kq = (idx & 7) * 4;
            int mg = m0g + m;
            const float4 xv = *(const float4*)&x[(size_t)mg * D + kk + kq];
            float4 pv;
            if ((mg % S) == 0) {
                int b = mg / S;
                pv = *(const float4*)&state[((size_t)b * rows + i1) * D + kk + kq];
            } else {
                pv = *(const float4*)&x[(size_t)(mg - 1) * D + kk + kq];
            }
            const float4 tm = *(const float4*)&tmx[kk + kq];
            xk_s[kq + 0][m] = xv.x + (pv.x - xv.x) * tm.x;
            xk_s[kq + 1][m] = xv.y + (pv.y - xv.y) * tm.y;
            xk_s[kq + 2][m] = xv.z + (pv.z - xv.z) * tm.z;
            xk_s[kq + 3][m] = xv.w + (pv.w - xv.w) * tm.w;
        }
        // stage W1 tile: 32k x 160n
        for (int idx = tid; idx < KC1 * NMIX / 4; idx += T1) {
            int k  = idx / 40;
            int n4 = (idx % 40) * 4;
            *(float4*)&w_s[k][n4] = *(const float4*)&W1[(size_t)(kk + k) * NMIX + n4];
        }
        __syncthreads();

#pragma unroll 8
        for (int k = 0; k < KC1; k++) {
            const float4 xa = *(const float4*)&xk_s[k][mt];
            const float4 xb = *(const float4*)&xk_s[k][mt + 4];
            const ulonglong2 wv = *(const ulonglong2*)&w_s[k][n0];
            ull xd;
            xd = pk2(xa.x, xa.x); acc[0][0] = f2fma(xd, wv.x, acc[0][0]); acc[0][1] = f2fma(xd, wv.y, acc[0][1]);
            xd = pk2(xa.y, xa.y); acc[1][0] = f2fma(xd, wv.x, acc[1][0]); acc[1][1] = f2fma(xd, wv.y, acc[1][1]);
            xd = pk2(xa.z, xa.z); acc[2][0] = f2fma(xd, wv.x, acc[2][0]); acc[2][1] = f2fma(xd, wv.y, acc[2][1]);
            xd = pk2(xa.w, xa.w); acc[3][0] = f2fma(xd, wv.x, acc[3][0]); acc[3][1] = f2fma(xd, wv.y, acc[3][1]);
            xd = pk2(xb.x, xb.x); acc[4][0] = f2fma(xd, wv.x, acc[4][0]); acc[4][1] = f2fma(xd, wv.y, acc[4][1]);
            xd = pk2(xb.y, xb.y); acc[5][0] = f2fma(xd, wv.x, acc[5][0]); acc[5][1] = f2fma(xd, wv.y, acc[5][1]);
            xd = pk2(xb.z, xb.z); acc[6][0] = f2fma(xd, wv.x, acc[6][0]); acc[6][1] = f2fma(xd, wv.y, acc[6][1]);
            xd = pk2(xb.w, xb.w); acc[7][0] = f2fma(xd, wv.x, acc[7][0]); acc[7][1] = f2fma(xd, wv.y, acc[7][1]);
        }
    }

#pragma unroll
    for (int r = 0; r < 8; r++) {
        float v0, v1, v2, v3;
        upk2(acc[r][0], v0, v1);
        upk2(acc[r][1], v2, v3);
        float4 o;
        o.x = tanhf(v0); o.y = tanhf(v1); o.z = tanhf(v2); o.w = tanhf(v3);
        *(float4*)&g_h[(size_t)(m0g + mt + r) * NMIX + n0] = o;
    }
}

// ---------------------------------------------------------------------------
// GEMM2 fused: out[m,f,d] = x + sx*(maa_f + sum_k h[m,f*32+k]*W2[f,k,d])
// block: 32 tokens x 256 d, 128 threads, thread: 2 d-cols, acc packed over
// token pairs (h transposed in smem -> LDS.128 gives 2 token-pairs direct).
// ---------------------------------------------------------------------------
__global__ void __launch_bounds__(T2) k_gemm2(
    const float* __restrict__ x, const float* __restrict__ state,
    const float* __restrict__ W2,
    const float* __restrict__ mk, const float* __restrict__ mw,
    const float* __restrict__ mv, const float* __restrict__ mr,
    const float* __restrict__ mg,
    const int* __restrict__ i_ptr, float* __restrict__ out,
    int S, int D, int rows)
{
    __shared__ float hT[NMIX][MT2 + 4];   // row 36 floats = 144B (16B-aligned)

    const int m0  = blockIdx.x * MT2;
    const int d0  = blockIdx.y * DT2;
    const int tid = threadIdx.x;
    const int d   = d0 + tid * C2;
    const int i1  = rows * i_ptr[0] + 1;

    // stage h transposed: 32 tokens x 160 cols
    for (int idx = tid; idx < MT2 * NMIX / 4; idx += T2) {
        int r  = idx / 40;
        int c4 = (idx % 40) * 4;
        const float4 hv = *(const float4*)&g_h[(size_t)(m0 + r) * NMIX + c4];
        hT[c4 + 0][r] = hv.x;
        hT[c4 + 1][r] = hv.y;
        hT[c4 + 2][r] = hv.z;
        hT[c4 + 3][r] = hv.w;
    }
    __syncthreads();

    const float* maa[5] = { mk, mw, mv, mr, mg };

#pragma unroll
    for (int f = 0; f < 5; f++) {
        ull acc[16][C2];
#pragma unroll
        for (int p = 0; p < 16; p++) { acc[p][0] = 0ull; acc[p][1] = 0ull; }

#pragma unroll 8
        for (int k = 0; k < 32; k++) {
            const float2 wv = *(const float2*)&W2[(size_t)(f * 32 + k) * D + d];
            const ull wd0 = pk2(wv.x, wv.x);
            const ull wd1 = pk2(wv.y, wv.y);
            const int c = f * 32 + k;
#pragma unroll
            for (int p = 0; p < 16; p += 2) {
                const ulonglong2 hp = *(const ulonglong2*)&hT[c][p * 2];
                acc[p][0]     = f2fma(hp.x, wd0, acc[p][0]);
                acc[p][1]     = f2fma(hp.x, wd1, acc[p][1]);
                acc[p + 1][0] = f2fma(hp.y, wd0, acc[p + 1][0]);
                acc[p + 1][1] = f2fma(hp.y, wd1, acc[p + 1][1]);
            }
        }

        const float2 mf = *(const float2*)&maa[f][d];
#pragma unroll 4
        for (int p = 0; p < 16; p++) {
            float a0, a1, b0, b1;
            upk2(acc[p][0], a0, a1);   // col d,   tokens 2p, 2p+1
            upk2(acc[p][1], b0, b1);   // col d+1, tokens 2p, 2p+1
#pragma unroll
            for (int e = 0; e < 2; e++) {
                const int mgl = m0 + 2 * p + e;
                const float2 xv = *(const float2*)&x[(size_t)mgl * D + d];
                float2 pv;
                if ((mgl % S) == 0) {
                    int b = mgl / S;
                    pv = *(const float2*)&state[((size_t)b * rows + i1) * D + d];
                } else {
                    pv = *(const float2*)&x[(size_t)(mgl - 1) * D + d];
                }
                const float ya = (e == 0) ? a0 : a1;
                const float yb = (e == 0) ? b0 : b1;
                float2 o;
                o.x = xv.x + (pv.x - xv.x) * (mf.x + ya);
                o.y = xv.y + (pv.y - xv.y) * (mf.y + yb);
                *(float2*)&out[((size_t)mgl * 5 + f) * D + d] = o;
            }
        }
    }
}

// ---------------------------------------------------------------------------
// state copy with row i1 <- x[:, S-1, :]
// ---------------------------------------------------------------------------
__global__ void k_state(const float* __restrict__ x,
                        const float* __restrict__ state,
                        const int* __restrict__ i_ptr,
                        float* __restrict__ out_state,
                        int S, int D, int rows, int total4)
{
    int idx = blockIdx.x * blockDim.x + threadIdx.x;
    if (idx >= total4) return;
    int e  = idx * 4;
    int dd = e % D;
    int r  = (e / D) % rows;
    int b  = e / (D * rows);
    int i1 = rows * i_ptr[0] + 1;
    float4 v;
    if (r == i1)
        v = *(const float4*)&x[((size_t)b * S + (S - 1)) * D + dd];
    else
        v = *(const float4*)&state[e];
    *(float4*)&out_state[e] = v;
}

// ---------------------------------------------------------------------------
extern "C" void kernel_launch(void* const* d_in, const int* in_sizes, int n_in,
                              void* d_out, int out_size)
{
    const float* x     = (const float*)d_in[0];
    const float* state = (const float*)d_in[1];
    const float* tmx   = (const float*)d_in[2];
    const float* W1    = (const float*)d_in[3];
    const float* W2    = (const float*)d_in[4];
    const float* mk    = (const float*)d_in[5];
    const float* mw    = (const float*)d_in[6];
    const float* mv    = (const float*)d_in[7];
    const float* mr    = (const float*)d_in[8];
    const float* mg    = (const float*)d_in[9];
    const int*   ip    = (const int*)d_in[10];

    const int D    = in_sizes[2];          // 2048
    const int M    = in_sizes[0] / D;      // 8192
    const int rows = 2 + D / 32;           // 66
    const int B    = in_sizes[1] / (rows * D);
    const int S    = M / B;

    float* out_x = (float*)d_out;
    const long long xsz = (long long)M * 5 * D;

    k_gemm1<<<M / BM1, T1>>>(x, state, tmx, W1, ip, S, D, rows);

    dim3 g2(M / MT2, D / DT2);
    k_gemm2<<<g2, T2>>>(x, state, W2, mk, mw, mv, mr, mg, ip, out_x, S, D, rows);

    if ((long long)out_size > xsz) {
        float* out_state = out_x + xsz;
        int total4 = (B * rows * D) / 4;
        k_state<<<(total4 + 255) / 256, 256>>>(x, state, ip, out_state, S, D, rows, total4);
    }
}

// round 3
// speedup vs baseline: 1.8231x; 1.4330x over previous
#include <cuda_runtime.h>

#define NMIX 160
// gemm1: 64-token tile, split-K=2, 32-k chunks, double buffered
#define KS   2
#define BM1  64
#define KC1  32
#define T1   320
#define XK_ROW (BM1 + 4)      // 68 floats
#define WD_ROW (2 * NMIX)     // 320 floats (duplicated weights)
// gemm2: 32-token x 512-d tile
#define MT2  32
#define T2   256
#define C2   2
#define DT2  (T2 * C2)        // 512

typedef unsigned long long ull;

__device__ __forceinline__ ull pk2(float a, float b) {
    ull r; asm("mov.b64 %0,{%1,%2};" : "=l"(r) : "f"(a), "f"(b)); return r;
}
__device__ __forceinline__ void upk2(ull v, float& a, float& b) {
    asm("mov.b64 {%0,%1},%2;" : "=f"(a), "=f"(b) : "l"(v));
}
__device__ __forceinline__ ull f2fma(ull a, ull b, ull c) {
    ull d; asm("fma.rn.f32x2 %0,%1,%2,%3;" : "=l"(d) : "l"(a), "l"(b), "l"(c)); return d;
}

// split-K partials of xk @ W1 (pre-tanh): [KS][M][NMIX], M = 8192
__device__ float g_part[KS * 8192 * NMIX];

// ---------------------------------------------------------------------------
// GEMM1 (split-K): partial[ks][m,n] = sum_{k in split} xk[m,k] * W1[k,n]
// 320 threads; thread tile = 4 token-pairs x 4 n; k-step = 4 LDS.128 + 16 FFMA2
// ---------------------------------------------------------------------------
__global__ void __launch_bounds__(T1, 2) k_gemm1(
    const float* __restrict__ x, const float* __restrict__ state,
    const float* __restrict__ tmx, const float* __restrict__ W1,
    const int* __restrict__ i_ptr, int S, int D, int rows, int Mtot)
{
    extern __shared__ float sm[];
    float* xkT = sm;                                 // [2][KC1][XK_ROW]
    float* wd  = sm + 2 * KC1 * XK_ROW;              // [2][KC1][WD_ROW]

    const int m0g   = blockIdx.x * BM1;
    const int kd    = D / KS;
    const int kbase = blockIdx.y * kd;
    const int tid   = threadIdx.x;
    const int n0    = (tid & 3) * 4 + (tid >> 5) * 16;   // 10 warps x 16 n = 160
    const int mt    = ((tid >> 2) & 7) * 8;              // 8 groups x 8 tokens
    const int i1    = rows * i_ptr[0] + 1;

    ull acc[4][4];
#pragma unroll
    for (int p = 0; p < 4; p++)
#pragma unroll
        for (int j = 0; j < 4; j++) acc[p][j] = 0ull;

    // staging registers
    float4 xv[2], pv[2], tv[2];
    int    xm[2], xk[2];
    bool   xon[2];
    float4 ws[4];
    int    wk[4], wn[4];

    const int nc = kd / KC1;

    // ---- prefetch helper (manually inlined twice) ----
#define PREFETCH(KB)                                                          \
    {                                                                         \
        _Pragma("unroll")                                                     \
        for (int it = 0; it < 2; it++) {                                      \
            int idx = tid + it * T1;                                          \
            xon[it] = idx < (BM1 * KC1 / 4);                                  \
            if (xon[it]) {                                                    \
                int m = idx >> 3, kq = (idx & 7) * 4;                         \
                int mg = m0g + m, g = (KB) + kq;                              \
                xm[it] = m; xk[it] = kq;                                      \
                xv[it] = *(const float4*)&x[(size_t)mg * D + g];              \
                if ((mg % S) == 0) {                                          \
                    int b = mg / S;                                           \
                    pv[it] = *(const float4*)&state[((size_t)b * rows + i1) * D + g]; \
                } else {                                                      \
                    pv[it] = *(const float4*)&x[(size_t)(mg - 1) * D + g];    \
                }                                                             \
                tv[it] = *(const float4*)&tmx[g];                             \
            }                                                                 \
        }                                                                     \
        _Pragma("unroll")                                                     \
        for (int it = 0; it < 4; it++) {                                      \
            int idx = tid + it * T1;                                          \
            int k = idx / 40, n4 = (idx % 40) * 4;                            \
            wk[it] = k; wn[it] = n4;                                          \
            ws[it] = *(const float4*)&W1[(size_t)((KB) + k) * NMIX + n4];     \
        }                                                                     \
    }

#define COMMIT(BUF)                                                           \
    {                                                                         \
        float* xb = xkT + (BUF) * (KC1 * XK_ROW);                             \
        float* wb = wd  + (BUF) * (KC1 * WD_ROW);                             \
        _Pragma("unroll")                                                     \
        for (int it = 0; it < 2; it++) {                                      \
            if (xon[it]) {                                                    \
                int m = xm[it], kq = xk[it];                                  \
                xb[(kq + 0) * XK_ROW + m] = xv[it].x + (pv[it].x - xv[it].x) * tv[it].x; \
                xb[(kq + 1) * XK_ROW + m] = xv[it].y + (pv[it].y - xv[it].y) * tv[it].y; \
                xb[(kq + 2) * XK_ROW + m] = xv[it].z + (pv[it].z - xv[it].z) * tv[it].z; \
                xb[(kq + 3) * XK_ROW + m] = xv[it].w + (pv[it].w - xv[it].w) * tv[it].w; \
            }                                                                 \
        }                                                                     \
        _Pragma("unroll")                                                     \
        for (int it = 0; it < 4; it++) {                                      \
            float4 d0 = make_float4(ws[it].x, ws[it].x, ws[it].y, ws[it].y);  \
            float4 d1 = make_float4(ws[it].z, ws[it].z, ws[it].w, ws[it].w);  \
            *(float4*)&wb[wk[it] * WD_ROW + 2 * wn[it]]     = d0;             \
            *(float4*)&wb[wk[it] * WD_ROW + 2 * wn[it] + 4] = d1;             \
        }                                                                     \
    }

    PREFETCH(kbase);
    COMMIT(0);

    for (int c = 0; c < nc; c++) {
        __syncthreads();
        const bool more = (c + 1 < nc);
        if (more) PREFETCH(kbase + (c + 1) * KC1);

        const float* xb = xkT + (c & 1) * (KC1 * XK_ROW);
        const float* wb = wd  + (c & 1) * (KC1 * WD_ROW);

#pragma unroll 16
        for (int k = 0; k < KC1; k++) {
            const ulonglong2 xp = *(const ulonglong2*)&xb[k * XK_ROW + mt];
            const ulonglong2 xq = *(const ulonglong2*)&xb[k * XK_ROW + mt + 4];
            const ulonglong2 wa = *(const ulonglong2*)&wb[k * WD_ROW + 2 * n0];
            const ulonglong2 wc = *(const ulonglong2*)&wb[k * WD_ROW + 2 * n0 + 4];
            acc[0][0] = f2fma(xp.x, wa.x, acc[0][0]);
            acc[0][1] = f2fma(xp.x, wa.y, acc[0][1]);
            acc[0][2] = f2fma(xp.x, wc.x, acc[0][2]);
            acc[0][3] = f2fma(xp.x, wc.y, acc[0][3]);
            acc[1][0] = f2fma(xp.y, wa.x, acc[1][0]);
            acc[1][1] = f2fma(xp.y, wa.y, acc[1][1]);
            acc[1][2] = f2fma(xp.y, wc.x, acc[1][2]);
            acc[1][3] = f2fma(xp.y, wc.y, acc[1][3]);
            acc[2][0] = f2fma(xq.x, wa.x, acc[2][0]);
            acc[2][1] = f2fma(xq.x, wa.y, acc[2][1]);
            acc[2][2] = f2fma(xq.x, wc.x, acc[2][2]);
            acc[2][3] = f2fma(xq.x, wc.y, acc[2][3]);
            acc[3][0] = f2fma(xq.y, wa.x, acc[3][0]);
            acc[3][1] = f2fma(xq.y, wa.y, acc[3][1]);
            acc[3][2] = f2fma(xq.y, wc.x, acc[3][2]);
            acc[3][3] = f2fma(xq.y, wc.y, acc[3][3]);
        }
        if (more) COMMIT((c + 1) & 1);
    }

    // store partials (pre-tanh) for this K-split
    float* gp = g_part + (size_t)blockIdx.y * Mtot * NMIX;
#pragma unroll
    for (int p = 0; p < 4; p++) {
        const int me = m0g + mt + 2 * p;
#pragma unroll
        for (int j = 0; j < 4; j++) {
            float ve, vo;
            upk2(acc[p][j], ve, vo);
            gp[(size_t)me * NMIX + n0 + j]       = ve;
            gp[(size_t)(me + 1) * NMIX + n0 + j] = vo;
        }
    }
#undef PREFETCH
#undef COMMIT
}

// ---------------------------------------------------------------------------
// GEMM2 fused: h = tanh(part0+part1); out[m,f,d] = x + sx*(maa_f + h@W2_f)
// 256 threads, 32-token x 512-d tile, all-broadcast LDS of transposed h
// ---------------------------------------------------------------------------
__global__ void __launch_bounds__(T2, 2) k_gemm2(
    const float* __restrict__ x, const float* __restrict__ state,
    const float* __restrict__ W2,
    const float* __restrict__ mk, const float* __restrict__ mw,
    const float* __restrict__ mv, const float* __restrict__ mr,
    const float* __restrict__ mg,
    const int* __restrict__ i_ptr, float* __restrict__ out,
    int S, int D, int rows, int Mtot)
{
    __shared__ float hT[NMIX][MT2 + 4];   // transposed h, 144B rows

    const int m0  = blockIdx.x * MT2;
    const int tid = threadIdx.x;
    const int d   = blockIdx.y * DT2 + tid * C2;
    const int i1  = rows * i_ptr[0] + 1;

    // stage: sum split-K partials, tanh, transpose
    for (int idx = tid; idx < MT2 * NMIX / 4; idx += T2) {
        int r  = idx / 40;
        int c4 = (idx % 40) * 4;
        const float4 a = *(const float4*)&g_part[(size_t)(m0 + r) * NMIX + c4];
        const float4 b = *(const float4*)&g_part[(size_t)(Mtot + m0 + r) * NMIX + c4];
        hT[c4 + 0][r] = tanhf(a.x + b.x);
        hT[c4 + 1][r] = tanhf(a.y + b.y);
        hT[c4 + 2][r] = tanhf(a.z + b.z);
        hT[c4 + 3][r] = tanhf(a.w + b.w);
    }
    __syncthreads();

    const float* maa[5] = { mk, mw, mv, mr, mg };

#pragma unroll 1
    for (int f = 0; f < 5; f++) {
        ull acc[16][2];
#pragma unroll
        for (int q = 0; q < 16; q++) { acc[q][0] = 0ull; acc[q][1] = 0ull; }

#pragma unroll 8
        for (int k = 0; k < 32; k++) {
            const float2 wv = *(const float2*)&W2[(size_t)(f * 32 + k) * D + d];
            const ull wd0 = pk2(wv.x, wv.x);
            const ull wd1 = pk2(wv.y, wv.y);
            const int c = f * 32 + k;
#pragma unroll
            for (int p = 0; p < 8; p++) {
                const ulonglong2 hp = *(const ulonglong2*)&hT[c][4 * p];
                acc[2*p][0]   = f2fma(hp.x, wd0, acc[2*p][0]);
                acc[2*p][1]   = f2fma(hp.x, wd1, acc[2*p][1]);
                acc[2*p+1][0] = f2fma(hp.y, wd0, acc[2*p+1][0]);
                acc[2*p+1][1] = f2fma(hp.y, wd1, acc[2*p+1][1]);
            }
        }

        const float2 mf = *(const float2*)&maa[f][d];
#pragma unroll 4
        for (int q = 0; q < 16; q++) {
            float a0, a1, b0, b1;
            upk2(acc[q][0], a0, a1);   // col d,   tokens 2q, 2q+1
            upk2(acc[q][1], b0, b1);   // col d+1, tokens 2q, 2q+1
#pragma unroll
            for (int e = 0; e < 2; e++) {
                const int mgl = m0 + 2 * q + e;
                const float2 xv = *(const float2*)&x[(size_t)mgl * D + d];
                float2 pv;
                if ((mgl % S) == 0) {
                    int b = mgl / S;
                    pv = *(const float2*)&state[((size_t)b * rows + i1) * D + d];
                } else {
                    pv = *(const float2*)&x[(size_t)(mgl - 1) * D + d];
                }
                const float ya = (e == 0) ? a0 : a1;
                const float yb = (e == 0) ? b0 : b1;
                float2 o;
                o.x = xv.x + (pv.x - xv.x) * (mf.x + ya);
                o.y = xv.y + (pv.y - xv.y) * (mf.y + yb);
                *(float2*)&out[((size_t)mgl * 5 + f) * D + d] = o;
            }
        }
    }
}

// ---------------------------------------------------------------------------
// state copy with row i1 <- x[:, S-1, :]
// ---------------------------------------------------------------------------
__global__ void k_state(const float* __restrict__ x,
                        const float* __restrict__ state,
                        const int* __restrict__ i_ptr,
                        float* __restrict__ out_state,
                        int S, int D, int rows, int total4)
{
    int idx = blockIdx.x * blockDim.x + threadIdx.x;
    if (idx >= total4) return;
    int e  = idx * 4;
    int dd = e % D;
    int r  = (e / D) % rows;
    int b  = e / (D * rows);
    int i1 = rows * i_ptr[0] + 1;
    float4 v;
    if (r == i1)
        v = *(const float4*)&x[((size_t)b * S + (S - 1)) * D + dd];
    else
        v = *(const float4*)&state[e];
    *(float4*)&out_state[e] = v;
}

// ---------------------------------------------------------------------------
extern "C" void kernel_launch(void* const* d_in, const int* in_sizes, int n_in,
                              void* d_out, int out_size)
{
    const float* x     = (const float*)d_in[0];
    const float* state = (const float*)d_in[1];
    const float* tmx   = (const float*)d_in[2];
    const float* W1    = (const float*)d_in[3];
    const float* W2    = (const float*)d_in[4];
    const float* mk    = (const float*)d_in[5];
    const float* mw    = (const float*)d_in[6];
    const float* mv    = (const float*)d_in[7];
    const float* mr    = (const float*)d_in[8];
    const float* mg    = (const float*)d_in[9];
    const int*   ip    = (const int*)d_in[10];

    const int D    = in_sizes[2];          // 2048
    const int M    = in_sizes[0] / D;      // 8192
    const int rows = 2 + D / 32;           // 66
    const int B    = in_sizes[1] / (rows * D);
    const int S    = M / B;

    float* out_x = (float*)d_out;
    const long long xsz = (long long)M * 5 * D;

    const int smem1 = (2 * KC1 * XK_ROW + 2 * KC1 * WD_ROW) * 4;   // 99328 B
    cudaFuncSetAttribute(k_gemm1, cudaFuncAttributeMaxDynamicSharedMemorySize, smem1);

    dim3 g1(M / BM1, KS);
    k_gemm1<<<g1, T1, smem1>>>(x, state, tmx, W1, ip, S, D, rows, M);

    dim3 g2(M / MT2, D / DT2);
    k_gemm2<<<g2, T2>>>(x, state, W2, mk, mw, mv, mr, mg, ip, out_x, S, D, rows, M);

    if ((long long)out_size > xsz) {
        float* out_state = out_x + xsz;
        int total4 = (B * rows * D) / 4;
        k_state<<<(total4 + 255) / 256, 256>>>(x, state, ip, out_state, S, D, rows, total4);
    }
}